// round 4
// baseline (speedup 1.0000x reference)
#include <cuda_runtime.h>
#include <cuda_bf16.h>
#include <cstdint>

#define N_DE 12288
#define M_X  2048
#define DIM  128
#define TILE 128
#define T_BLOCKS (N_DE / TILE)                      // 96
#define KXX_BLOCKS (T_BLOCKS * (T_BLOCKS + 1) / 2)  // 4656
#define M_TILES (M_X / TILE)                        // 16

// exp(-0.5/10 * d2) = exp2(C2 * d2)
__device__ const float C2 = -0.07213475204444817f;
// poly for exp(-d2/1024) = e^{-0.3} * Taylor5(z), z = 0.3 - d2/1024
__device__ const float KZ = -0.0009765625f;  // -1/1024
__device__ const float P0 = 0.7408182206817179f;
__device__ const float P1 = 0.7408182206817179f;
__device__ const float P2 = 0.37040911034085893f;
__device__ const float P3 = 0.12346970344695298f;
__device__ const float P4 = 0.030867425861738245f;
__device__ const float P5 = 0.006173485172347649f;

__device__ __align__(16) uint8_t g_De_f8[N_DE * DIM];
__device__ __align__(16) uint8_t g_X_f8[M_X * DIM];
__device__ float  g_sq_de[N_DE];
__device__ float  g_sq_x[M_X];
__device__ double g_kxx;
__device__ float  g_kxy[M_X];

// ---------------------------------------------------------------- scalar helpers
__device__ __forceinline__ float ex2f(float x) {
    float y;
    asm("ex2.approx.ftz.f32 %0, %1;" : "=f"(y) : "f"(x));
    return y;
}

// ---------------------------------------------------------------- f32x2 helpers
typedef unsigned long long ull;
__device__ __forceinline__ ull pk2(float lo, float hi) {
    ull r; asm("mov.b64 %0, {%1,%2};" : "=l"(r) : "f"(lo), "f"(hi)); return r;
}
__device__ __forceinline__ void upk2(ull v, float& lo, float& hi) {
    asm("mov.b64 {%0,%1}, %2;" : "=f"(lo), "=f"(hi) : "l"(v));
}
__device__ __forceinline__ ull fma2(ull a, ull b, ull c) {
    ull d; asm("fma.rn.f32x2 %0, %1, %2, %3;" : "=l"(d) : "l"(a), "l"(b), "l"(c)); return d;
}
__device__ __forceinline__ ull add2(ull a, ull b) {
    ull d; asm("add.rn.f32x2 %0, %1, %2;" : "=l"(d) : "l"(a), "l"(b)); return d;
}
__device__ __forceinline__ ull mul2(ull a, ull b) {
    ull d; asm("mul.rn.f32x2 %0, %1, %2;" : "=l"(d) : "l"(a), "l"(b)); return d;
}

// ---------------- prep: fp32 -> e4m3 + exact fp32 row norms + zero accumulators -----
__global__ void prep_kernel(const float* __restrict__ De, const float* __restrict__ X) {
    if (blockIdx.x == 0) {
        for (int i = threadIdx.x; i < M_X; i += blockDim.x) g_kxy[i] = 0.f;
        if (threadIdx.x == 0) g_kxx = 0.0;
    }
    int warp = (blockIdx.x * blockDim.x + threadIdx.x) >> 5;
    int lane = threadIdx.x & 31;
    if (warp >= N_DE + M_X) return;

    const float* src;
    uint8_t* dst;
    float* sq;
    if (warp < N_DE) {
        src = De + (size_t)warp * DIM;
        dst = g_De_f8 + (size_t)warp * DIM;
        sq  = g_sq_de + warp;
    } else {
        int r = warp - N_DE;
        src = X + (size_t)r * DIM;
        dst = g_X_f8 + (size_t)r * DIM;
        sq  = g_sq_x + r;
    }
    float4 v = ((const float4*)src)[lane];
    float s = v.x * v.x + v.y * v.y + v.z * v.z + v.w * v.w;
    unsigned short h0, h1;
    asm("cvt.rn.satfinite.e4m3x2.f32 %0, %1, %2;" : "=h"(h0) : "f"(v.y), "f"(v.x));
    asm("cvt.rn.satfinite.e4m3x2.f32 %0, %1, %2;" : "=h"(h1) : "f"(v.w), "f"(v.z));
    ((unsigned*)dst)[lane] = ((unsigned)h1 << 16) | (unsigned)h0;
#pragma unroll
    for (int o = 16; o; o >>= 1) s += __shfl_xor_sync(0xffffffffu, s, o);
    if (lane == 0) *sq = s;
}

// ---------------- fp8 tile helpers ----------------------------------------------------
// smem tile: 128 rows x 128 bytes, 16B-chunk XOR swizzle (8 chunks/row)
__device__ __forceinline__ unsigned sw8(unsigned sbase, int r, int cb) {
    int chunk = (cb >> 4) ^ (r & 7);
    return sbase + (unsigned)((r << 7) + (chunk << 4) + (cb & 15));
}

__device__ __forceinline__ void ldm4(unsigned addr, unsigned& r0, unsigned& r1,
                                     unsigned& r2, unsigned& r3) {
    asm volatile("ldmatrix.sync.aligned.m8n8.x4.shared.b16 {%0,%1,%2,%3}, [%4];"
                 : "=r"(r0), "=r"(r1), "=r"(r2), "=r"(r3)
                 : "r"(addr));
}

__device__ __forceinline__ void mma_fp8(float* c, unsigned a0, unsigned a1, unsigned a2,
                                        unsigned a3, unsigned b0, unsigned b1) {
    asm volatile(
        "mma.sync.aligned.m16n8k32.row.col.f32.e4m3.e4m3.f32 "
        "{%0,%1,%2,%3},{%4,%5,%6,%7},{%8,%9},{%0,%1,%2,%3};"
        : "+f"(c[0]), "+f"(c[1]), "+f"(c[2]), "+f"(c[3])
        : "r"(a0), "r"(a1), "r"(a2), "r"(a3), "r"(b0), "r"(b1));
}

// 128x128B fp8 tile: global row-major (8 uint4/row) -> swizzled smem
__device__ __forceinline__ void load_tile(uint8_t* s, const uint8_t* g) {
    int t = threadIdx.x;
#pragma unroll
    for (int i = 0; i < 4; i++) {
        int id = t + i * 256;
        int r = id >> 3, c = id & 7;
        uint4 v = ((const uint4*)g)[id];
        *(uint4*)(s + (r << 7) + ((c ^ (r & 7)) << 4)) = v;
    }
}

// full-K (128B) warp GEMM: 64x32 output per warp, fp8 e4m3, 4 k-chunks of 32B
__device__ __forceinline__ void gemm_tile(unsigned sA, unsigned sB, int wm, int wn, int lane,
                                          float (&acc)[4][4][4]) {
    int lrA = lane & 15, aOff = (lane >> 4) << 4;
    int grp = lane >> 3, w8 = lane & 7;
    int rB = ((grp & 2) << 2) + w8;
    int cBb = (grp & 1) << 4;
#pragma unroll
    for (int kk = 0; kk < 4; kk++) {
        int k0 = kk << 5;
        unsigned a[4][4];
#pragma unroll
        for (int mi = 0; mi < 4; mi++)
            ldm4(sw8(sA, wm + mi * 16 + lrA, k0 + aOff),
                 a[mi][0], a[mi][1], a[mi][2], a[mi][3]);
        unsigned b[4][2];
        {
            unsigned q0, q1, q2, q3;
            ldm4(sw8(sB, wn + rB, k0 + cBb), q0, q1, q2, q3);
            b[0][0] = q0; b[0][1] = q1; b[1][0] = q2; b[1][1] = q3;
            ldm4(sw8(sB, wn + 16 + rB, k0 + cBb), q0, q1, q2, q3);
            b[2][0] = q0; b[2][1] = q1; b[3][0] = q2; b[3][1] = q3;
        }
#pragma unroll
        for (int mi = 0; mi < 4; mi++)
#pragma unroll
            for (int ni = 0; ni < 4; ni++)
                mma_fp8(acc[mi][ni], a[mi][0], a[mi][1], a[mi][2], a[mi][3],
                        b[ni][0], b[ni][1]);
    }
}

// packed RBF: in d2 pair -> term1 poly added to sum1 (packed), term2 via EX2 to t2a/t2b
__device__ __forceinline__ void rbf2(ull a01, ull srp, ull scp, ull KZ2, ull C32, ull c5p,
                                     ull c4p, ull c3p, ull c2p, ull c1p, ull c0p, ull M2P,
                                     ull CT2, ull& sum1, float& t2a, float& t2b) {
    ull s = add2(srp, scp);
    ull d2 = fma2(M2P, a01, s);
    ull z = fma2(KZ2, d2, C32);
    ull p = fma2(c5p, z, c4p);
    p = fma2(p, z, c3p);
    p = fma2(p, z, c2p);
    p = fma2(p, z, c1p);
    p = fma2(p, z, c0p);
    sum1 = add2(sum1, p);
    ull ag = mul2(CT2, d2);
    float alo, ahi;
    upk2(ag, alo, ahi);
    t2a += ex2f(alo);
    t2b += ex2f(ahi);
}

#define RBF_CONSTS                                                        \
    const ull KZ2 = pk2(KZ, KZ), C32 = pk2(0.3f, 0.3f);                   \
    const ull c5p = pk2(P5, P5), c4p = pk2(P4, P4), c3p = pk2(P3, P3);    \
    const ull c2p = pk2(P2, P2), c1p = pk2(P1, P1), c0p = pk2(P0, P0);    \
    const ull M2P = pk2(-2.f, -2.f), CT2 = pk2(C2, C2);

// ---------------- kxx: upper-triangular tiles of De x De ----------------------------
__global__ void __launch_bounds__(256, 2) kxx_kernel() {
    __shared__ __align__(16) uint8_t As[TILE * DIM];
    __shared__ __align__(16) uint8_t Bs[TILE * DIM];
    __shared__ float sqa[TILE], sqb[TILE];
    __shared__ float s_bsum;

    int t = threadIdx.x;
    int lane = t & 31, warp = t >> 5;

    int tb = blockIdx.x;
    const int Tn = T_BLOCKS;
    int bi = (int)((2 * Tn + 1 - sqrtf((float)((2 * Tn + 1) * (2 * Tn + 1) - 8 * tb))) * 0.5f);
    while (bi * Tn - bi * (bi - 1) / 2 > tb) bi--;
    while ((bi + 1) * Tn - (bi + 1) * bi / 2 <= tb) bi++;
    int bj = bi + (tb - (bi * Tn - bi * (bi - 1) / 2));

    if (t == 0) s_bsum = 0.f;
    load_tile(As, g_De_f8 + (size_t)bi * TILE * DIM);
    load_tile(Bs, g_De_f8 + (size_t)bj * TILE * DIM);
    if (t < 128) sqa[t] = g_sq_de[bi * TILE + t];
    else         sqb[t - 128] = g_sq_de[bj * TILE + (t - 128)];
    __syncthreads();

    int wm = (warp >> 2) * 64;
    int wn = (warp & 3) * 32;
    float acc[4][4][4];
#pragma unroll
    for (int i = 0; i < 4; i++)
#pragma unroll
        for (int j = 0; j < 4; j++)
#pragma unroll
            for (int e = 0; e < 4; e++) acc[i][j][e] = 0.f;

    unsigned sA = (unsigned)__cvta_generic_to_shared(As);
    unsigned sB = (unsigned)__cvta_generic_to_shared(Bs);
    gemm_tile(sA, sB, wm, wn, lane, acc);

    RBF_CONSTS
    int r0 = wm + (lane >> 2);
    int c0 = wn + ((lane & 3) << 1);
    ull scp[4];
#pragma unroll
    for (int ni = 0; ni < 4; ni++) scp[ni] = pk2(sqb[c0 + ni * 8], sqb[c0 + ni * 8 + 1]);

    ull sum1 = pk2(0.f, 0.f);
    float t2a = 0.f, t2b = 0.f;
#pragma unroll
    for (int mi = 0; mi < 4; mi++) {
        float sr0 = sqa[r0 + mi * 16];
        float sr1 = sqa[r0 + mi * 16 + 8];
        ull sr0p = pk2(sr0, sr0), sr1p = pk2(sr1, sr1);
#pragma unroll
        for (int ni = 0; ni < 4; ni++) {
            rbf2(pk2(acc[mi][ni][0], acc[mi][ni][1]), sr0p, scp[ni], KZ2, C32, c5p, c4p,
                 c3p, c2p, c1p, c0p, M2P, CT2, sum1, t2a, t2b);
            rbf2(pk2(acc[mi][ni][2], acc[mi][ni][3]), sr1p, scp[ni], KZ2, C32, c5p, c4p,
                 c3p, c2p, c1p, c0p, M2P, CT2, sum1, t2a, t2b);
        }
    }
    float slo, shi;
    upk2(sum1, slo, shi);
    float s = slo + shi + t2a + t2b;
#pragma unroll
    for (int o = 16; o; o >>= 1) s += __shfl_xor_sync(0xffffffffu, s, o);
    if (lane == 0) atomicAdd(&s_bsum, s);
    __syncthreads();
    if (t == 0) {
        double w = (bi == bj) ? 1.0 : 2.0;
        atomicAdd(&g_kxx, w * (double)s_bsum);
    }
}

// ---------------- kxy: X x De, per-row sums ------------------------------------------
__global__ void __launch_bounds__(256, 2) kxy_kernel() {
    __shared__ __align__(16) uint8_t As[TILE * DIM];
    __shared__ __align__(16) uint8_t Bs[TILE * DIM];
    __shared__ float sqa[TILE], sqb[TILE], srow[TILE];

    int t = threadIdx.x;
    int lane = t & 31, warp = t >> 5;
    int bn = blockIdx.x, bm = blockIdx.y;

    load_tile(As, g_X_f8 + (size_t)bm * TILE * DIM);
    load_tile(Bs, g_De_f8 + (size_t)bn * TILE * DIM);
    if (t < 128) { sqa[t] = g_sq_x[bm * TILE + t]; srow[t] = 0.f; }
    else         { sqb[t - 128] = g_sq_de[bn * TILE + (t - 128)]; }
    __syncthreads();

    int wm = (warp >> 2) * 64;
    int wn = (warp & 3) * 32;
    float acc[4][4][4];
#pragma unroll
    for (int i = 0; i < 4; i++)
#pragma unroll
        for (int j = 0; j < 4; j++)
#pragma unroll
            for (int e = 0; e < 4; e++) acc[i][j][e] = 0.f;

    unsigned sA = (unsigned)__cvta_generic_to_shared(As);
    unsigned sB = (unsigned)__cvta_generic_to_shared(Bs);
    gemm_tile(sA, sB, wm, wn, lane, acc);

    RBF_CONSTS
    int r0 = wm + (lane >> 2);
    int c0 = wn + ((lane & 3) << 1);
    ull scp[4];
#pragma unroll
    for (int ni = 0; ni < 4; ni++) scp[ni] = pk2(sqb[c0 + ni * 8], sqb[c0 + ni * 8 + 1]);

#pragma unroll
    for (int mi = 0; mi < 4; mi++) {
        float sr0 = sqa[r0 + mi * 16];
        float sr1 = sqa[r0 + mi * 16 + 8];
        ull sr0p = pk2(sr0, sr0), sr1p = pk2(sr1, sr1);
        ull sumA = pk2(0.f, 0.f), sumB = pk2(0.f, 0.f);
        float t2a0 = 0.f, t2b0 = 0.f, t2a1 = 0.f, t2b1 = 0.f;
#pragma unroll
        for (int ni = 0; ni < 4; ni++) {
            rbf2(pk2(acc[mi][ni][0], acc[mi][ni][1]), sr0p, scp[ni], KZ2, C32, c5p, c4p,
                 c3p, c2p, c1p, c0p, M2P, CT2, sumA, t2a0, t2b0);
            rbf2(pk2(acc[mi][ni][2], acc[mi][ni][3]), sr1p, scp[ni], KZ2, C32, c5p, c4p,
                 c3p, c2p, c1p, c0p, M2P, CT2, sumB, t2a1, t2b1);
        }
        float lo, hi;
        upk2(sumA, lo, hi);
        float v0 = lo + hi + t2a0 + t2b0;
        upk2(sumB, lo, hi);
        float v1 = lo + hi + t2a1 + t2b1;
        v0 += __shfl_xor_sync(0xffffffffu, v0, 1);
        v0 += __shfl_xor_sync(0xffffffffu, v0, 2);
        v1 += __shfl_xor_sync(0xffffffffu, v1, 1);
        v1 += __shfl_xor_sync(0xffffffffu, v1, 2);
        if ((lane & 3) == 0) {
            int row = wm + mi * 16 + (lane >> 2);
            atomicAdd(&srow[row], v0);
            atomicAdd(&srow[row + 8], v1);
        }
    }
    __syncthreads();
    if (t < 128) atomicAdd(&g_kxy[bm * TILE + t], srow[t]);
}

// ---------------- finalize -----------------------------------------------------------
__global__ void final_kernel(float* __restrict__ out) {
    int m = blockIdx.x * blockDim.x + threadIdx.x;
    if (m < M_X) {
        float kxx_mean = (float)(g_kxx / ((double)N_DE * (double)N_DE));
        out[m] = kxx_mean + 2.0f - 2.0f * (g_kxy[m] * (1.0f / (float)N_DE));
    }
}

extern "C" void kernel_launch(void* const* d_in, const int* in_sizes, int n_in,
                              void* d_out, int out_size) {
    const float* De = (const float*)d_in[0];
    const float* X  = (const float*)d_in[1];
    float* out = (float*)d_out;

    prep_kernel<<<(N_DE + M_X) / 4, 128>>>(De, X);
    kxx_kernel<<<KXX_BLOCKS, 256>>>();
    kxy_kernel<<<dim3(T_BLOCKS, M_TILES), 256>>>();
    final_kernel<<<(M_X + 255) / 256, 256>>>(out);
}